// round 2
// baseline (speedup 1.0000x reference)
#include <cuda_runtime.h>
#include <cstdint>

#define LEVELS 2
#define BATCH  16
#define DIM    256
#define TLEN   2048
#define NPTS   (BATCH * TLEN)      // 32768 points per level
#define KCODES 1024
#define NELEM  (BATCH * DIM * TLEN) // 8388608 per level

#define PTILE 128
#define CTILE 128
#define DSTEP 16
#define GATHER_BLOCKS (BATCH * (TLEN / 32))  // 1024 per level
#define TAU 0.02f

// ---------------- scratch (no allocations allowed) ----------------
__device__ int   g_idx[LEVELS][NPTS];
__device__ float g_cnorm[LEVELS][KCODES];
__device__ float g_partial[LEVELS][GATHER_BLOCKS];
__device__ int   g_refine_count[LEVELS];
__device__ int   g_refine_list[LEVELS][NPTS];

// ---------------- f32x2 helpers (sm_103a packed FP32) ----------------
__device__ __forceinline__ unsigned long long pk2(float a) {
    unsigned long long r;
    unsigned int u = __float_as_uint(a);
    asm("mov.b64 %0, {%1, %1};" : "=l"(r) : "r"(u));
    return r;
}
__device__ __forceinline__ void fma2(unsigned long long& acc,
                                     unsigned long long a,
                                     unsigned long long b) {
    asm("fma.rn.f32x2 %0, %1, %2, %0;" : "+l"(acc) : "l"(a), "l"(b));
}
__device__ __forceinline__ void unpk2(unsigned long long v, float& lo, float& hi) {
    unsigned int l, h;
    asm("mov.b64 {%0, %1}, %2;" : "=r"(l), "=r"(h) : "l"(v));
    lo = __uint_as_float(l);
    hi = __uint_as_float(h);
}

// ---------------- kernel 1: codebook row squared norms + counter reset ----------------
__global__ void cnorm_kernel(const float* __restrict__ cb_top,
                             const float* __restrict__ cb_bot) {
    int lvl = blockIdx.y;
    if (blockIdx.x == 0 && threadIdx.x == 0) g_refine_count[lvl] = 0;
    const float* cb = lvl ? cb_bot : cb_top;
    int w = threadIdx.x >> 5, lane = threadIdx.x & 31;
    int c = blockIdx.x * 8 + w;
    const float* row = cb + (size_t)c * DIM;
    float s = 0.f;
#pragma unroll
    for (int i = 0; i < DIM / 32; i++) {
        float v = row[i * 32 + lane];
        s = fmaf(v, v, s);
    }
#pragma unroll
    for (int o = 16; o; o >>= 1) s += __shfl_down_sync(0xffffffffu, s, o);
    if (lane == 0) g_cnorm[lvl][c] = s;
}

// ---------------- kernel 2: GEMM + argmin (tracks top-2 for refinement) ----------------
__device__ __forceinline__ void prefetch_tiles(
    const float* __restrict__ hbase, const float* __restrict__ cb,
    int d0, int c0, int rA0, int cA0, int rB0, int cB0,
    float4& fa0, float4& fa1, float4& fb0, float4& fb1) {
    fa0 = *(const float4*)(hbase + (size_t)(d0 + rA0) * TLEN + cA0);
    fa1 = *(const float4*)(hbase + (size_t)(d0 + rA0 + 8) * TLEN + cA0);
    fb0 = *(const float4*)(cb + (size_t)(c0 + rB0) * DIM + d0 + cB0);
    fb1 = *(const float4*)(cb + (size_t)(c0 + rB0 + 64) * DIM + d0 + cB0);
}

__global__ __launch_bounds__(256)
void argmin_kernel(const float* __restrict__ h_top, const float* __restrict__ h_bot,
                   const float* __restrict__ cb_top, const float* __restrict__ cb_bot) {
    __shared__ __align__(16) float As[DSTEP * PTILE];   // [dd][p]
    __shared__ __align__(16) float Bs[DSTEP * CTILE];   // [dd][c]
    __shared__ __align__(16) float C2s[16 * PTILE];     // second-best staging

    int lvl = blockIdx.y;
    const float* h  = lvl ? h_bot  : h_top;
    const float* cb = lvl ? cb_bot : cb_top;
    const float* cn = g_cnorm[lvl];

    int tid = threadIdx.x;
    int n0 = blockIdx.x * PTILE;            // t-tile within one b (2048 % 128 == 0)
    int b  = n0 / TLEN;
    int t0 = n0 % TLEN;
    const float* hbase = h + (size_t)b * DIM * TLEN + t0;

    int rA0 = tid >> 5;          // 0..7  (second load adds 8)
    int cA0 = (tid & 31) * 4;
    int rB0 = tid >> 2;          // 0..63 (second load adds 64)
    int cB0 = (tid & 3) * 4;

    int ty = tid >> 4, tx = tid & 15;

    float bestv[8], best2v[8];
    int   besti[8];
#pragma unroll
    for (int i = 0; i < 8; i++) { bestv[i] = 3.4e38f; best2v[i] = 3.4e38f; besti[i] = 0; }

    float4 fa0, fa1, fb0, fb1;
    prefetch_tiles(hbase, cb, 0, 0, rA0, cA0, rB0, cB0, fa0, fa1, fb0, fb1);

    for (int ct = 0; ct < KCODES / CTILE; ct++) {
        int c0 = ct * CTILE;
        unsigned long long acc[8][4];
#pragma unroll
        for (int i = 0; i < 8; i++)
#pragma unroll
            for (int j = 0; j < 4; j++) acc[i][j] = 0ull;

        for (int ds = 0; ds < DIM / DSTEP; ds++) {
            __syncthreads();
            *(float4*)&As[rA0 * PTILE + cA0]       = fa0;
            *(float4*)&As[(rA0 + 8) * PTILE + cA0] = fa1;
            Bs[(cB0 + 0) * CTILE + rB0] = fb0.x;
            Bs[(cB0 + 1) * CTILE + rB0] = fb0.y;
            Bs[(cB0 + 2) * CTILE + rB0] = fb0.z;
            Bs[(cB0 + 3) * CTILE + rB0] = fb0.w;
            Bs[(cB0 + 0) * CTILE + rB0 + 64] = fb1.x;
            Bs[(cB0 + 1) * CTILE + rB0 + 64] = fb1.y;
            Bs[(cB0 + 2) * CTILE + rB0 + 64] = fb1.z;
            Bs[(cB0 + 3) * CTILE + rB0 + 64] = fb1.w;
            __syncthreads();

            int nds = ds + 1, nct = ct;
            if (nds == DIM / DSTEP) { nds = 0; nct++; }
            if (nct < KCODES / CTILE)
                prefetch_tiles(hbase, cb, nds * DSTEP, nct * CTILE,
                               rA0, cA0, rB0, cB0, fa0, fa1, fb0, fb1);

#pragma unroll
            for (int dd = 0; dd < DSTEP; dd++) {
                float4 a0 = *(const float4*)&As[dd * PTILE + ty * 4];
                float4 a1 = *(const float4*)&As[dd * PTILE + 64 + ty * 4];
                ulonglong2 b0 = *(const ulonglong2*)&Bs[dd * CTILE + tx * 4];
                ulonglong2 b1 = *(const ulonglong2*)&Bs[dd * CTILE + 64 + tx * 4];
                unsigned long long ap;
                ap = pk2(a0.x); fma2(acc[0][0],ap,b0.x); fma2(acc[0][1],ap,b0.y); fma2(acc[0][2],ap,b1.x); fma2(acc[0][3],ap,b1.y);
                ap = pk2(a0.y); fma2(acc[1][0],ap,b0.x); fma2(acc[1][1],ap,b0.y); fma2(acc[1][2],ap,b1.x); fma2(acc[1][3],ap,b1.y);
                ap = pk2(a0.z); fma2(acc[2][0],ap,b0.x); fma2(acc[2][1],ap,b0.y); fma2(acc[2][2],ap,b1.x); fma2(acc[2][3],ap,b1.y);
                ap = pk2(a0.w); fma2(acc[3][0],ap,b0.x); fma2(acc[3][1],ap,b0.y); fma2(acc[3][2],ap,b1.x); fma2(acc[3][3],ap,b1.y);
                ap = pk2(a1.x); fma2(acc[4][0],ap,b0.x); fma2(acc[4][1],ap,b0.y); fma2(acc[4][2],ap,b1.x); fma2(acc[4][3],ap,b1.y);
                ap = pk2(a1.y); fma2(acc[5][0],ap,b0.x); fma2(acc[5][1],ap,b0.y); fma2(acc[5][2],ap,b1.x); fma2(acc[5][3],ap,b1.y);
                ap = pk2(a1.z); fma2(acc[6][0],ap,b0.x); fma2(acc[6][1],ap,b0.y); fma2(acc[6][2],ap,b1.x); fma2(acc[6][3],ap,b1.y);
                ap = pk2(a1.w); fma2(acc[7][0],ap,b0.x); fma2(acc[7][1],ap,b0.y); fma2(acc[7][2],ap,b1.x); fma2(acc[7][3],ap,b1.y);
            }
        }

        // fold into running top-2 (ascending c within thread -> first-min tie-break)
        float cnr[8];
#pragma unroll
        for (int i = 0; i < 4; i++) {
            cnr[i]     = cn[c0 + tx * 4 + i];
            cnr[4 + i] = cn[c0 + 64 + tx * 4 + i];
        }
#pragma unroll
        for (int pi = 0; pi < 8; pi++) {
#pragma unroll
            for (int cj = 0; cj < 4; cj++) {
                float lo, hi;
                unpk2(acc[pi][cj], lo, hi);
                int cloc = (cj < 2) ? (tx * 4 + cj * 2) : (64 + tx * 4 + (cj - 2) * 2);
                int cg = c0 + cloc;
                int ni = (cj < 2) ? (cj * 2) : (4 + (cj - 2) * 2);
                float d0v = fmaf(-2.f, lo, cnr[ni]);
                float d1v = fmaf(-2.f, hi, cnr[ni + 1]);
                if (d0v < bestv[pi]) { best2v[pi] = bestv[pi]; bestv[pi] = d0v; besti[pi] = cg; }
                else if (d0v < best2v[pi]) best2v[pi] = d0v;
                if (d1v < bestv[pi]) { best2v[pi] = bestv[pi]; bestv[pi] = d1v; besti[pi] = cg + 1; }
                else if (d1v < best2v[pi]) best2v[pi] = d1v;
            }
        }
    }

    // cross-thread top-2 merge over the 16 tx columns per point row
    __syncthreads();
    float* cv = As;              // 16*128 floats
    int*   ci = (int*)Bs;        // 16*128 ints
#pragma unroll
    for (int pi = 0; pi < 8; pi++) {
        int p = (pi < 4) ? (ty * 4 + pi) : (64 + ty * 4 + pi - 4);
        cv[tx * PTILE + p]  = bestv[pi];
        ci[tx * PTILE + p]  = besti[pi];
        C2s[tx * PTILE + p] = best2v[pi];
    }
    __syncthreads();
    if (tid < PTILE) {
        float bv = cv[tid];
        int   bi = ci[tid];
        float b2 = C2s[tid];
#pragma unroll
        for (int x = 1; x < 16; x++) {
            float v  = cv[x * PTILE + tid];
            int   ii = ci[x * PTILE + tid];
            float v2 = C2s[x * PTILE + tid];
            if (v < bv || (v == bv && ii < bi)) {
                b2 = fminf(bv, v2);
                bv = v; bi = ii;
            } else {
                b2 = fminf(b2, v);
            }
        }
        g_idx[lvl][n0 + tid] = bi;
        if (b2 - bv < TAU) {
            int pos = atomicAdd(&g_refine_count[lvl], 1);
            g_refine_list[lvl][pos] = n0 + tid;
        }
    }
}

// ---------------- kernel 2b: f64 exact refinement of near-ties ----------------
__global__ __launch_bounds__(256)
void refine_kernel(const float* __restrict__ h_top, const float* __restrict__ h_bot,
                   const float* __restrict__ cb_top, const float* __restrict__ cb_bot) {
    int lvl = blockIdx.y;
    const float* h  = lvl ? h_bot  : h_top;
    const float* cb = lvl ? cb_bot : cb_top;
    int cnt = g_refine_count[lvl];

    __shared__ double xs[DIM];
    __shared__ double rv[8];
    __shared__ int    ri[8];

    int tid = threadIdx.x;
    int w = tid >> 5, lane = tid & 31;

    for (int e = blockIdx.x; e < cnt; e += gridDim.x) {
        int p = g_refine_list[lvl][e];
        int b = p / TLEN, t = p % TLEN;
        __syncthreads();
        if (tid < DIM)
            xs[tid] = (double)h[((size_t)b * DIM + tid) * TLEN + t];
        __syncthreads();

        // warp w handles ascending code range [w*128, (w+1)*128)
        double bv = 1e300;
        int    bi = 0;
        for (int k = 0; k < KCODES / 8; k++) {
            int c = w * (KCODES / 8) + k;
            const float* row = cb + (size_t)c * DIM;
            double s = 0.0;
#pragma unroll
            for (int i = 0; i < DIM / 32; i++) {
                int d = i * 32 + lane;
                double diff = xs[d] - (double)row[d];
                s = fma(diff, diff, s);
            }
#pragma unroll
            for (int o = 16; o; o >>= 1) s += __shfl_down_sync(0xffffffffu, s, o);
            s = __shfl_sync(0xffffffffu, s, 0);
            if (s < bv) { bv = s; bi = c; }   // strict < keeps first occurrence
        }
        if (lane == 0) { rv[w] = bv; ri[w] = bi; }
        __syncthreads();
        if (tid == 0) {
            double fbv = rv[0]; int fbi = ri[0];
#pragma unroll
            for (int x = 1; x < 8; x++) {
                if (rv[x] < fbv || (rv[x] == fbv && ri[x] < fbi)) { fbv = rv[x]; fbi = ri[x]; }
            }
            g_idx[lvl][p] = fbi;
        }
    }
}

// ---------------- kernel 3: gather z_q + per-block loss partials ----------------
__global__ __launch_bounds__(256)
void gather_kernel(const float* __restrict__ h_top, const float* __restrict__ h_bot,
                   const float* __restrict__ cb_top, const float* __restrict__ cb_bot,
                   float* __restrict__ out) {
    int lvl = blockIdx.z;
    const float* h  = lvl ? h_bot  : h_top;
    const float* cb = lvl ? cb_bot : cb_top;
    float* z = out + (size_t)lvl * NELEM;

    int b = blockIdx.y;
    int t0 = blockIdx.x * 32;
    int tid = threadIdx.x;

    __shared__ int   sidx[32];
    __shared__ float sh[32 * 33];
    __shared__ float red[256];

    if (tid < 32) sidx[tid] = g_idx[lvl][b * TLEN + t0 + tid];
    __syncthreads();

    float lacc = 0.f;
    int j2 = tid >> 3, l8 = tid & 7;

    for (int dc = 0; dc < DIM; dc += 32) {
        float4 v = *(const float4*)(cb + (size_t)sidx[j2] * DIM + dc + l8 * 4);
        sh[(l8 * 4 + 0) * 33 + j2] = v.x;
        sh[(l8 * 4 + 1) * 33 + j2] = v.y;
        sh[(l8 * 4 + 2) * 33 + j2] = v.z;
        sh[(l8 * 4 + 3) * 33 + j2] = v.w;
        __syncthreads();
#pragma unroll
        for (int it = 0; it < 4; it++) {
            int i = tid + it * 256;
            int dl = i >> 5, j = i & 31;
            size_t off = ((size_t)b * DIM + dc + dl) * TLEN + t0 + j;
            float zz = sh[dl * 33 + j];
            z[off] = zz;
            float e = h[off] - zz;
            lacc = fmaf(e, e, lacc);
        }
        __syncthreads();
    }

    red[tid] = lacc;
    __syncthreads();
#pragma unroll
    for (int s = 128; s; s >>= 1) {
        if (tid < s) red[tid] += red[tid + s];
        __syncthreads();
    }
    if (tid == 0) g_partial[lvl][blockIdx.y * (TLEN / 32) + blockIdx.x] = red[0];
}

// ---------------- kernel 4: finalize scalars ----------------
__global__ __launch_bounds__(1024)
void finalize_kernel(float* __restrict__ out) {
    __shared__ int   hist[KCODES];
    __shared__ float red[1024];
    int tid = threadIdx.x;

    float sums[2];
#pragma unroll
    for (int lvl = 0; lvl < 2; lvl++) {
        red[tid] = g_partial[lvl][tid];
        __syncthreads();
        for (int s = 512; s; s >>= 1) {
            if (tid < s) red[tid] += red[tid + s];
            __syncthreads();
        }
        sums[lvl] = red[0];
        __syncthreads();
    }
    float loss = sums[0] * (1.f / (float)NELEM) + sums[1] * (1.f / (float)NELEM);

    float ppl[2];
#pragma unroll
    for (int lvl = 0; lvl < 2; lvl++) {
        hist[tid] = 0;
        __syncthreads();
#pragma unroll
        for (int i = 0; i < NPTS / 1024; i++)
            atomicAdd(&hist[g_idx[lvl][i * 1024 + tid]], 1);
        __syncthreads();
        float p = (float)hist[tid] * (1.f / (float)NPTS);
        red[tid] = p * logf(p + 1e-10f);
        __syncthreads();
        for (int s = 512; s; s >>= 1) {
            if (tid < s) red[tid] += red[tid + s];
            __syncthreads();
        }
        ppl[lvl] = expf(-red[0]);
        __syncthreads();
    }

    if (tid == 0) {
        size_t base = (size_t)2 * NELEM;
        out[base + 0] = loss;      // vq_loss
        out[base + 1] = loss;      // commitment_loss (numerically identical)
        out[base + 2] = ppl[0];    // perplexity_top
        out[base + 3] = ppl[1];    // perplexity_bot
    }
}

// ---------------- launcher ----------------
extern "C" void kernel_launch(void* const* d_in, const int* in_sizes, int n_in,
                              void* d_out, int out_size) {
    const float* h_top  = (const float*)d_in[0];
    const float* h_bot  = (const float*)d_in[1];
    const float* cb_top = (const float*)d_in[2];
    const float* cb_bot = (const float*)d_in[3];
    float* out = (float*)d_out;

    cnorm_kernel<<<dim3(KCODES / 8, LEVELS), 256>>>(cb_top, cb_bot);
    argmin_kernel<<<dim3(NPTS / PTILE, LEVELS), 256>>>(h_top, h_bot, cb_top, cb_bot);
    refine_kernel<<<dim3(256, LEVELS), 256>>>(h_top, h_bot, cb_top, cb_bot);
    gather_kernel<<<dim3(TLEN / 32, BATCH, LEVELS), 256>>>(h_top, h_bot, cb_top, cb_bot, out);
    finalize_kernel<<<1, 1024>>>(out);
}